// round 13
// baseline (speedup 1.0000x reference)
#include <cuda_runtime.h>

#define HID 128
#define MAXN 100000

__device__ float g_XA[(size_t)MAXN * HID];
__device__ float g_XB[(size_t)MAXN * HID];

extern __shared__ float smem[];

// 128x128x128 fp32 GEMM core, 512 threads, 8x4 micro-tile per thread.
// r0 = warp*8 (A-row loads are warp-uniform broadcasts), c0 = lane*4
// (W float4 loads conflict-free across the 32 lanes).
__device__ __forceinline__ void gemm_tile512(const float* __restrict__ sA,
                                             const float* __restrict__ sW,
                                             int r0, int c0, float acc[8][4]) {
#pragma unroll 4
    for (int k = 0; k < HID; k += 4) {
        float4 a[8];
#pragma unroll
        for (int i = 0; i < 8; i++)
            a[i] = *(const float4*)(sA + (r0 + i) * HID + k);
#pragma unroll
        for (int j = 0; j < 4; j++) {
            float4 w = *(const float4*)(sW + (k + j) * HID + c0);
#pragma unroll
            for (int i = 0; i < 8; i++) {
                float av = (j == 0) ? a[i].x : (j == 1) ? a[i].y
                         : (j == 2) ? a[i].z : a[i].w;
                acc[i][0] = fmaf(av, w.x, acc[i][0]);
                acc[i][1] = fmaf(av, w.y, acc[i][1]);
                acc[i][2] = fmaf(av, w.z, acc[i][2]);
                acc[i][3] = fmaf(av, w.w, acc[i][3]);
            }
        }
    }
}

// ---------------------------------------------------------------------------
// Node kernel: XA = x @ W1[0:128,:], XB = x @ W1[128:256,:]
// smem: sX 64KB + sW 128KB = 192KB, 512 threads
// ---------------------------------------------------------------------------
__global__ void __launch_bounds__(512)
node_kernel(const float* __restrict__ x, const float* __restrict__ W1,
            int n_nodes) {
    float* sX = smem;               // 128 x 128
    float* sW = smem + 128 * HID;   // 256 x 128 (W1 rows 0..255)
    const int tid  = threadIdx.x;
    const int row0 = blockIdx.x * 128;

    for (int i = tid; i < 128 * 32; i += 512) {
        int r = i >> 5;
        int c4 = i & 31;
        float4 v = make_float4(0.f, 0.f, 0.f, 0.f);
        if (row0 + r < n_nodes)
            v = ((const float4*)(x + (size_t)(row0 + r) * HID))[c4];
        ((float4*)sX)[i] = v;
    }
    for (int i = tid; i < 256 * 32; i += 512)
        ((float4*)sW)[i] = ((const float4*)W1)[i];
    __syncthreads();

    const int r0 = (tid >> 5) * 8;
    const int c0 = (tid & 31) * 4;

#pragma unroll
    for (int half = 0; half < 2; half++) {
        const float* Wp = sW + half * HID * HID;
        float acc[8][4];
#pragma unroll
        for (int i = 0; i < 8; i++)
#pragma unroll
            for (int j = 0; j < 4; j++) acc[i][j] = 0.f;

        gemm_tile512(sX, Wp, r0, c0, acc);

        float* dst = (half == 0) ? g_XA : g_XB;
#pragma unroll
        for (int i = 0; i < 8; i++) {
            int r = row0 + r0 + i;
            if (r < n_nodes)
                *(float4*)(dst + (size_t)r * HID + c0) =
                    make_float4(acc[i][0], acc[i][1], acc[i][2], acc[i][3]);
        }
    }
}

// ---------------------------------------------------------------------------
// Fused edge kernel: one 512-thread CTA per 128-edge tile.
// smem: sEdge 64KB + sW 64KB + sBuf 64KB = 192KB
// ---------------------------------------------------------------------------
__global__ void __launch_bounds__(512)
edge_kernel(const float* __restrict__ edge, const int* __restrict__ ei,
            const float* __restrict__ W1,  const float* __restrict__ b1,
            const float* __restrict__ g1,  const float* __restrict__ be1,
            const float* __restrict__ W2,  const float* __restrict__ b2,
            const float* __restrict__ g2,  const float* __restrict__ be2,
            float* __restrict__ out, int n_edges) {
    float* sEdge = smem;                 // 128 x 128 (edge tile, kept for residual)
    float* sW    = smem + 128 * HID;     // 128 x 128 (W1c, then W2)
    float* sBuf  = smem + 2 * 128 * HID; // 128 x 128 (gather -> pre1 -> h1 -> pre2)

    const int tid  = threadIdx.x;
    const int wid  = tid >> 5;   // 0..15
    const int lane = tid & 31;
    const int e0   = blockIdx.x * 128;

    // W1c = W1 rows 256..383
    for (int i = tid; i < 128 * 32; i += 512)
        ((float4*)sW)[i] = ((const float4*)(W1 + 256 * HID))[i];

    // Edge tile + gathered node transforms (+b1) into sBuf.
    {
        float4 bv = ((const float4*)b1)[lane];
        for (int r = wid; r < 128; r += 16) {
            int e = e0 + r;
            if (e < n_edges) {
                float4 ev = ((const float4*)(edge + (size_t)e * HID))[lane];
                ((float4*)(sEdge + r * HID))[lane] = ev;
                int s = ei[e];
                int d = ei[n_edges + e];
                float4 va = ((const float4*)(g_XA + (size_t)s * HID))[lane];
                float4 vb = ((const float4*)(g_XB + (size_t)d * HID))[lane];
                ((float4*)(sBuf + r * HID))[lane] =
                    make_float4(va.x + vb.x + bv.x, va.y + vb.y + bv.y,
                                va.z + vb.z + bv.z, va.w + vb.w + bv.w);
            } else {
                ((float4*)(sEdge + r * HID))[lane] = make_float4(0.f, 0.f, 0.f, 0.f);
                ((float4*)(sBuf  + r * HID))[lane] = make_float4(0.f, 0.f, 0.f, 0.f);
            }
        }
    }
    __syncthreads();

    const int r0 = (tid >> 5) * 8;
    const int c0 = (tid & 31) * 4;

    // ---- GEMM1: acc = edge @ W1c ----
    float acc[8][4];
#pragma unroll
    for (int i = 0; i < 8; i++)
#pragma unroll
        for (int j = 0; j < 4; j++) acc[i][j] = 0.f;
    gemm_tile512(sEdge, sW, r0, c0, acc);

    // acc += gathered partials (own float4s only)
#pragma unroll
    for (int i = 0; i < 8; i++) {
        float4 gvv = *(const float4*)(sBuf + (r0 + i) * HID + c0);
        acc[i][0] += gvv.x; acc[i][1] += gvv.y;
        acc[i][2] += gvv.z; acc[i][3] += gvv.w;
    }
    __syncthreads();  // all GEMM1 reads of sW/sBuf done
#pragma unroll
    for (int i = 0; i < 8; i++)
        *(float4*)(sBuf + (r0 + i) * HID + c0) =
            make_float4(acc[i][0], acc[i][1], acc[i][2], acc[i][3]);
    __syncthreads();

    // ---- LN1 + SiLU (warp per row), and reload sW with W2 ----
    {
        float4 gv = ((const float4*)g1)[lane];
        float4 bev = ((const float4*)be1)[lane];
        for (int r = wid; r < 128; r += 16) {
            float4 v = ((float4*)(sBuf + r * HID))[lane];
            float s  = v.x + v.y + v.z + v.w;
            float ss = fmaf(v.x, v.x, fmaf(v.y, v.y, fmaf(v.z, v.z, v.w * v.w)));
#pragma unroll
            for (int o = 16; o > 0; o >>= 1) {
                s  += __shfl_xor_sync(0xffffffffu, s, o);
                ss += __shfl_xor_sync(0xffffffffu, ss, o);
            }
            float mean = s * (1.f / HID);
            float var  = ss * (1.f / HID) - mean * mean;
            float rstd = rsqrtf(var + 1e-5f);
            float y0 = (v.x - mean) * rstd * gv.x + bev.x;
            float y1 = (v.y - mean) * rstd * gv.y + bev.y;
            float y2 = (v.z - mean) * rstd * gv.z + bev.z;
            float y3 = (v.w - mean) * rstd * gv.w + bev.w;
            v.x = y0 / (1.f + __expf(-y0));
            v.y = y1 / (1.f + __expf(-y1));
            v.z = y2 / (1.f + __expf(-y2));
            v.w = y3 / (1.f + __expf(-y3));
            ((float4*)(sBuf + r * HID))[lane] = v;
        }
    }
    for (int i = tid; i < 128 * 32; i += 512)
        ((float4*)sW)[i] = ((const float4*)W2)[i];
    __syncthreads();

    // ---- GEMM2: acc = h1 @ W2 + b2 ----
#pragma unroll
    for (int i = 0; i < 8; i++)
#pragma unroll
        for (int j = 0; j < 4; j++) acc[i][j] = 0.f;
    gemm_tile512(sBuf, sW, r0, c0, acc);
    {
        float4 b2v = *(const float4*)(b2 + c0);
#pragma unroll
        for (int i = 0; i < 8; i++) {
            acc[i][0] += b2v.x; acc[i][1] += b2v.y;
            acc[i][2] += b2v.z; acc[i][3] += b2v.w;
        }
    }
    __syncthreads();  // all GEMM2 reads of sBuf done
#pragma unroll
    for (int i = 0; i < 8; i++)
        *(float4*)(sBuf + (r0 + i) * HID + c0) =
            make_float4(acc[i][0], acc[i][1], acc[i][2], acc[i][3]);
    __syncthreads();

    // ---- LN2 + tanh + residual -> global ----
    {
        float4 gv = ((const float4*)g2)[lane];
        float4 bev = ((const float4*)be2)[lane];
        for (int r = wid; r < 128; r += 16) {
            float4 v = ((float4*)(sBuf + r * HID))[lane];
            float s  = v.x + v.y + v.z + v.w;
            float ss = fmaf(v.x, v.x, fmaf(v.y, v.y, fmaf(v.z, v.z, v.w * v.w)));
#pragma unroll
            for (int o = 16; o > 0; o >>= 1) {
                s  += __shfl_xor_sync(0xffffffffu, s, o);
                ss += __shfl_xor_sync(0xffffffffu, ss, o);
            }
            float mean = s * (1.f / HID);
            float var  = ss * (1.f / HID) - mean * mean;
            float rstd = rsqrtf(var + 1e-5f);
            int e = e0 + r;
            if (e < n_edges) {
                float4 ev = ((float4*)(sEdge + r * HID))[lane];
                float4 o4;
                o4.x = ev.x + tanhf((v.x - mean) * rstd * gv.x + bev.x);
                o4.y = ev.y + tanhf((v.y - mean) * rstd * gv.y + bev.y);
                o4.z = ev.z + tanhf((v.z - mean) * rstd * gv.z + bev.z);
                o4.w = ev.w + tanhf((v.w - mean) * rstd * gv.w + bev.w);
                ((float4*)(out + (size_t)e * HID))[lane] = o4;
            }
        }
    }
}

extern "C" void kernel_launch(void* const* d_in, const int* in_sizes, int n_in,
                              void* d_out, int out_size) {
    const float* x   = (const float*)d_in[0];
    const int*   ei  = (const int*)d_in[1];      // edge_index: int32
    const float* edg = (const float*)d_in[2];
    const float* W1  = (const float*)d_in[3];
    const float* b1  = (const float*)d_in[4];
    const float* g1  = (const float*)d_in[5];
    const float* be1 = (const float*)d_in[6];
    const float* W2  = (const float*)d_in[7];
    const float* b2  = (const float*)d_in[8];
    const float* g2  = (const float*)d_in[9];
    const float* be2 = (const float*)d_in[10];
    float* out = (float*)d_out;

    int n_nodes = in_sizes[0] / HID;
    int n_edges = in_sizes[2] / HID;
    if (n_nodes > MAXN) n_nodes = MAXN;

    const int SMEM = 3 * 128 * HID * (int)sizeof(float);  // 196608
    cudaFuncSetAttribute(node_kernel, cudaFuncAttributeMaxDynamicSharedMemorySize, SMEM);
    cudaFuncSetAttribute(edge_kernel, cudaFuncAttributeMaxDynamicSharedMemorySize, SMEM);

    int node_blocks = (n_nodes + 127) / 128;
    int edge_blocks = (n_edges + 127) / 128;

    node_kernel<<<node_blocks, 512, SMEM>>>(x, W1, n_nodes);
    edge_kernel<<<edge_blocks, 512, SMEM>>>(edg, ei, W1, b1, g1, be1,
                                            W2, b2, g2, be2, out, n_edges);
}

// round 14
// speedup vs baseline: 1.0046x; 1.0046x over previous
#include <cuda_runtime.h>

#define HID 128
#define MAXN 100000

__device__ float g_XA[(size_t)MAXN * HID];
__device__ float g_XB[(size_t)MAXN * HID];

extern __shared__ float smem[];

// 128x128x128 fp32 GEMM core, 512 threads, 8x4 micro-tile per thread.
// r0 = warp*8 (A-row loads are warp-uniform broadcasts), c0 = lane*4
// (W float4 loads conflict-free across the 32 lanes).
__device__ __forceinline__ void gemm_tile512(const float* __restrict__ sA,
                                             const float* __restrict__ sW,
                                             int r0, int c0, float acc[8][4]) {
#pragma unroll 4
    for (int k = 0; k < HID; k += 4) {
        float4 a[8];
#pragma unroll
        for (int i = 0; i < 8; i++)
            a[i] = *(const float4*)(sA + (r0 + i) * HID + k);
#pragma unroll
        for (int j = 0; j < 4; j++) {
            float4 w = *(const float4*)(sW + (k + j) * HID + c0);
#pragma unroll
            for (int i = 0; i < 8; i++) {
                float av = (j == 0) ? a[i].x : (j == 1) ? a[i].y
                         : (j == 2) ? a[i].z : a[i].w;
                acc[i][0] = fmaf(av, w.x, acc[i][0]);
                acc[i][1] = fmaf(av, w.y, acc[i][1]);
                acc[i][2] = fmaf(av, w.z, acc[i][2]);
                acc[i][3] = fmaf(av, w.w, acc[i][3]);
            }
        }
    }
}

// ---------------------------------------------------------------------------
// Node kernel: XA = x @ W1[0:128,:], XB = x @ W1[128:256,:]
// smem: sX 64KB + sW 128KB = 192KB, 512 threads
// ---------------------------------------------------------------------------
__global__ void __launch_bounds__(512)
node_kernel(const float* __restrict__ x, const float* __restrict__ W1,
            int n_nodes) {
    float* sX = smem;               // 128 x 128
    float* sW = smem + 128 * HID;   // 256 x 128 (W1 rows 0..255)
    const int tid  = threadIdx.x;
    const int row0 = blockIdx.x * 128;

    for (int i = tid; i < 128 * 32; i += 512) {
        int r = i >> 5;
        int c4 = i & 31;
        float4 v = make_float4(0.f, 0.f, 0.f, 0.f);
        if (row0 + r < n_nodes)
            v = ((const float4*)(x + (size_t)(row0 + r) * HID))[c4];
        ((float4*)sX)[i] = v;
    }
    for (int i = tid; i < 256 * 32; i += 512)
        ((float4*)sW)[i] = ((const float4*)W1)[i];
    __syncthreads();

    const int r0 = (tid >> 5) * 8;
    const int c0 = (tid & 31) * 4;

#pragma unroll
    for (int half = 0; half < 2; half++) {
        const float* Wp = sW + half * HID * HID;
        float acc[8][4];
#pragma unroll
        for (int i = 0; i < 8; i++)
#pragma unroll
            for (int j = 0; j < 4; j++) acc[i][j] = 0.f;

        gemm_tile512(sX, Wp, r0, c0, acc);

        float* dst = (half == 0) ? g_XA : g_XB;
#pragma unroll
        for (int i = 0; i < 8; i++) {
            int r = row0 + r0 + i;
            if (r < n_nodes)
                *(float4*)(dst + (size_t)r * HID + c0) =
                    make_float4(acc[i][0], acc[i][1], acc[i][2], acc[i][3]);
        }
    }
}

// ---------------------------------------------------------------------------
// Fused edge kernel: one 512-thread CTA per 128-edge tile.
// smem: sEdge 64KB + sW 64KB + sBuf 64KB = 192KB
// ---------------------------------------------------------------------------
__global__ void __launch_bounds__(512)
edge_kernel(const float* __restrict__ edge, const int* __restrict__ ei,
            const float* __restrict__ W1,  const float* __restrict__ b1,
            const float* __restrict__ g1,  const float* __restrict__ be1,
            const float* __restrict__ W2,  const float* __restrict__ b2,
            const float* __restrict__ g2,  const float* __restrict__ be2,
            float* __restrict__ out, int n_edges) {
    float* sEdge = smem;                 // 128 x 128 (edge tile, kept for residual)
    float* sW    = smem + 128 * HID;     // 128 x 128 (W1c, then W2)
    float* sBuf  = smem + 2 * 128 * HID; // 128 x 128 (gather -> pre1 -> h1 -> pre2)

    const int tid  = threadIdx.x;
    const int wid  = tid >> 5;   // 0..15
    const int lane = tid & 31;
    const int e0   = blockIdx.x * 128;

    // W1c = W1 rows 256..383
    for (int i = tid; i < 128 * 32; i += 512)
        ((float4*)sW)[i] = ((const float4*)(W1 + 256 * HID))[i];

    // Edge tile + gathered node transforms (+b1) into sBuf.
    {
        float4 bv = ((const float4*)b1)[lane];
        for (int r = wid; r < 128; r += 16) {
            int e = e0 + r;
            if (e < n_edges) {
                float4 ev = ((const float4*)(edge + (size_t)e * HID))[lane];
                ((float4*)(sEdge + r * HID))[lane] = ev;
                int s = ei[e];
                int d = ei[n_edges + e];
                float4 va = ((const float4*)(g_XA + (size_t)s * HID))[lane];
                float4 vb = ((const float4*)(g_XB + (size_t)d * HID))[lane];
                ((float4*)(sBuf + r * HID))[lane] =
                    make_float4(va.x + vb.x + bv.x, va.y + vb.y + bv.y,
                                va.z + vb.z + bv.z, va.w + vb.w + bv.w);
            } else {
                ((float4*)(sEdge + r * HID))[lane] = make_float4(0.f, 0.f, 0.f, 0.f);
                ((float4*)(sBuf  + r * HID))[lane] = make_float4(0.f, 0.f, 0.f, 0.f);
            }
        }
    }
    __syncthreads();

    const int r0 = (tid >> 5) * 8;
    const int c0 = (tid & 31) * 4;

    // ---- GEMM1: acc = edge @ W1c ----
    float acc[8][4];
#pragma unroll
    for (int i = 0; i < 8; i++)
#pragma unroll
        for (int j = 0; j < 4; j++) acc[i][j] = 0.f;
    gemm_tile512(sEdge, sW, r0, c0, acc);

    // acc += gathered partials (own float4s only)
#pragma unroll
    for (int i = 0; i < 8; i++) {
        float4 gvv = *(const float4*)(sBuf + (r0 + i) * HID + c0);
        acc[i][0] += gvv.x; acc[i][1] += gvv.y;
        acc[i][2] += gvv.z; acc[i][3] += gvv.w;
    }
    __syncthreads();  // all GEMM1 reads of sW/sBuf done
#pragma unroll
    for (int i = 0; i < 8; i++)
        *(float4*)(sBuf + (r0 + i) * HID + c0) =
            make_float4(acc[i][0], acc[i][1], acc[i][2], acc[i][3]);
    __syncthreads();

    // ---- LN1 + SiLU (warp per row), and reload sW with W2 ----
    {
        float4 gv = ((const float4*)g1)[lane];
        float4 bev = ((const float4*)be1)[lane];
        for (int r = wid; r < 128; r += 16) {
            float4 v = ((float4*)(sBuf + r * HID))[lane];
            float s  = v.x + v.y + v.z + v.w;
            float ss = fmaf(v.x, v.x, fmaf(v.y, v.y, fmaf(v.z, v.z, v.w * v.w)));
#pragma unroll
            for (int o = 16; o > 0; o >>= 1) {
                s  += __shfl_xor_sync(0xffffffffu, s, o);
                ss += __shfl_xor_sync(0xffffffffu, ss, o);
            }
            float mean = s * (1.f / HID);
            float var  = ss * (1.f / HID) - mean * mean;
            float rstd = rsqrtf(var + 1e-5f);
            float y0 = (v.x - mean) * rstd * gv.x + bev.x;
            float y1 = (v.y - mean) * rstd * gv.y + bev.y;
            float y2 = (v.z - mean) * rstd * gv.z + bev.z;
            float y3 = (v.w - mean) * rstd * gv.w + bev.w;
            v.x = y0 / (1.f + __expf(-y0));
            v.y = y1 / (1.f + __expf(-y1));
            v.z = y2 / (1.f + __expf(-y2));
            v.w = y3 / (1.f + __expf(-y3));
            ((float4*)(sBuf + r * HID))[lane] = v;
        }
    }
    for (int i = tid; i < 128 * 32; i += 512)
        ((float4*)sW)[i] = ((const float4*)W2)[i];
    __syncthreads();

    // ---- GEMM2: acc = h1 @ W2 + b2 ----
#pragma unroll
    for (int i = 0; i < 8; i++)
#pragma unroll
        for (int j = 0; j < 4; j++) acc[i][j] = 0.f;
    gemm_tile512(sBuf, sW, r0, c0, acc);
    {
        float4 b2v = *(const float4*)(b2 + c0);
#pragma unroll
        for (int i = 0; i < 8; i++) {
            acc[i][0] += b2v.x; acc[i][1] += b2v.y;
            acc[i][2] += b2v.z; acc[i][3] += b2v.w;
        }
    }
    __syncthreads();  // all GEMM2 reads of sBuf done
#pragma unroll
    for (int i = 0; i < 8; i++)
        *(float4*)(sBuf + (r0 + i) * HID + c0) =
            make_float4(acc[i][0], acc[i][1], acc[i][2], acc[i][3]);
    __syncthreads();

    // ---- LN2 + tanh + residual -> global ----
    {
        float4 gv = ((const float4*)g2)[lane];
        float4 bev = ((const float4*)be2)[lane];
        for (int r = wid; r < 128; r += 16) {
            float4 v = ((float4*)(sBuf + r * HID))[lane];
            float s  = v.x + v.y + v.z + v.w;
            float ss = fmaf(v.x, v.x, fmaf(v.y, v.y, fmaf(v.z, v.z, v.w * v.w)));
#pragma unroll
            for (int o = 16; o > 0; o >>= 1) {
                s  += __shfl_xor_sync(0xffffffffu, s, o);
                ss += __shfl_xor_sync(0xffffffffu, ss, o);
            }
            float mean = s * (1.f / HID);
            float var  = ss * (1.f / HID) - mean * mean;
            float rstd = rsqrtf(var + 1e-5f);
            int e = e0 + r;
            if (e < n_edges) {
                float4 ev = ((float4*)(sEdge + r * HID))[lane];
                float4 o4;
                o4.x = ev.x + tanhf((v.x - mean) * rstd * gv.x + bev.x);
                o4.y = ev.y + tanhf((v.y - mean) * rstd * gv.y + bev.y);
                o4.z = ev.z + tanhf((v.z - mean) * rstd * gv.z + bev.z);
                o4.w = ev.w + tanhf((v.w - mean) * rstd * gv.w + bev.w);
                ((float4*)(out + (size_t)e * HID))[lane] = o4;
            }
        }
    }
}

extern "C" void kernel_launch(void* const* d_in, const int* in_sizes, int n_in,
                              void* d_out, int out_size) {
    const float* x   = (const float*)d_in[0];
    const int*   ei  = (const int*)d_in[1];      // edge_index: int32
    const float* edg = (const float*)d_in[2];
    const float* W1  = (const float*)d_in[3];
    const float* b1  = (const float*)d_in[4];
    const float* g1  = (const float*)d_in[5];
    const float* be1 = (const float*)d_in[6];
    const float* W2  = (const float*)d_in[7];
    const float* b2  = (const float*)d_in[8];
    const float* g2  = (const float*)d_in[9];
    const float* be2 = (const float*)d_in[10];
    float* out = (float*)d_out;

    int n_nodes = in_sizes[0] / HID;
    int n_edges = in_sizes[2] / HID;
    if (n_nodes > MAXN) n_nodes = MAXN;

    const int SMEM = 3 * 128 * HID * (int)sizeof(float);  // 196608
    cudaFuncSetAttribute(node_kernel, cudaFuncAttributeMaxDynamicSharedMemorySize, SMEM);
    cudaFuncSetAttribute(edge_kernel, cudaFuncAttributeMaxDynamicSharedMemorySize, SMEM);

    int node_blocks = (n_nodes + 127) / 128;
    int edge_blocks = (n_edges + 127) / 128;

    node_kernel<<<node_blocks, 512, SMEM>>>(x, W1, n_nodes);
    edge_kernel<<<edge_blocks, 512, SMEM>>>(edg, ei, W1, b1, g1, be1,
                                            W2, b2, g2, be2, out, n_edges);
}

// round 15
// speedup vs baseline: 1.0320x; 1.0272x over previous
#include <cuda_runtime.h>

#define HID 128
#define MAXN 100000

__device__ float g_XA[(size_t)MAXN * HID];
__device__ float g_XB[(size_t)MAXN * HID];

extern __shared__ float smem[];

// ---- packed f32x2 helpers (Blackwell FFMA2: 2 fp32 FMAs per instruction) ----
__device__ __forceinline__ unsigned long long dup_f32(float v) {
    unsigned long long r;
    asm("mov.b64 %0, {%1, %1};" : "=l"(r) : "f"(v));
    return r;
}
__device__ __forceinline__ void fma2(unsigned long long& d,
                                     unsigned long long a,
                                     unsigned long long b) {
    asm("fma.rn.f32x2 %0, %1, %2, %0;" : "+l"(d) : "l"(a), "l"(b));
}
__device__ __forceinline__ float2 unpk(unsigned long long v) {
    float2 p;
    asm("mov.b64 {%0, %1}, %2;" : "=f"(p.x), "=f"(p.y) : "l"(v));
    return p;
}

// 128x128x128 fp32 GEMM core, 512 threads, 8x4 micro-tile per thread.
// r0 = warp*8 (A-row LDS are warp-uniform broadcasts), c0 = lane*4
// (W loads: one LDS.128 per k, conflict-free; reinterpreted as two packed
// f32x2 column-pairs). Inner product uses fma.rn.f32x2 -> 2x fma-pipe FLOPs.
__device__ __forceinline__ void gemm_tile512(const float* __restrict__ sA,
                                             const float* __restrict__ sW,
                                             int r0, int c0, float accf[8][4]) {
    unsigned long long acc[8][2];
#pragma unroll
    for (int i = 0; i < 8; i++) { acc[i][0] = 0ull; acc[i][1] = 0ull; }

#pragma unroll 2
    for (int k = 0; k < HID; k += 4) {
        float4 a[8];
#pragma unroll
        for (int i = 0; i < 8; i++)
            a[i] = *(const float4*)(sA + (r0 + i) * HID + k);
#pragma unroll
        for (int j = 0; j < 4; j++) {
            ulonglong2 w = *(const ulonglong2*)(sW + (k + j) * HID + c0);
#pragma unroll
            for (int i = 0; i < 8; i++) {
                float av = (j == 0) ? a[i].x : (j == 1) ? a[i].y
                         : (j == 2) ? a[i].z : a[i].w;
                unsigned long long ad = dup_f32(av);
                fma2(acc[i][0], ad, w.x);
                fma2(acc[i][1], ad, w.y);
            }
        }
    }
#pragma unroll
    for (int i = 0; i < 8; i++) {
        float2 p0 = unpk(acc[i][0]);
        float2 p1 = unpk(acc[i][1]);
        accf[i][0] = p0.x; accf[i][1] = p0.y;
        accf[i][2] = p1.x; accf[i][3] = p1.y;
    }
}

// ---------------------------------------------------------------------------
// Node kernel: XA = x @ W1[0:128,:], XB = x @ W1[128:256,:]
// smem: sX 64KB + sW 128KB = 192KB, 512 threads
// ---------------------------------------------------------------------------
__global__ void __launch_bounds__(512)
node_kernel(const float* __restrict__ x, const float* __restrict__ W1,
            int n_nodes) {
    float* sX = smem;               // 128 x 128
    float* sW = smem + 128 * HID;   // 256 x 128 (W1 rows 0..255)
    const int tid  = threadIdx.x;
    const int row0 = blockIdx.x * 128;

    for (int i = tid; i < 128 * 32; i += 512) {
        int r = i >> 5;
        int c4 = i & 31;
        float4 v = make_float4(0.f, 0.f, 0.f, 0.f);
        if (row0 + r < n_nodes)
            v = ((const float4*)(x + (size_t)(row0 + r) * HID))[c4];
        ((float4*)sX)[i] = v;
    }
    for (int i = tid; i < 256 * 32; i += 512)
        ((float4*)sW)[i] = ((const float4*)W1)[i];
    __syncthreads();

    const int r0 = (tid >> 5) * 8;
    const int c0 = (tid & 31) * 4;

#pragma unroll
    for (int half = 0; half < 2; half++) {
        const float* Wp = sW + half * HID * HID;
        float acc[8][4];
        gemm_tile512(sX, Wp, r0, c0, acc);

        float* dst = (half == 0) ? g_XA : g_XB;
#pragma unroll
        for (int i = 0; i < 8; i++) {
            int r = row0 + r0 + i;
            if (r < n_nodes)
                *(float4*)(dst + (size_t)r * HID + c0) =
                    make_float4(acc[i][0], acc[i][1], acc[i][2], acc[i][3]);
        }
    }
}

// ---------------------------------------------------------------------------
// Fused edge kernel: one 512-thread CTA per 128-edge tile.
// smem: sEdge 64KB + sW 64KB + sBuf 64KB = 192KB
// ---------------------------------------------------------------------------
__global__ void __launch_bounds__(512)
edge_kernel(const float* __restrict__ edge, const int* __restrict__ ei,
            const float* __restrict__ W1,  const float* __restrict__ b1,
            const float* __restrict__ g1,  const float* __restrict__ be1,
            const float* __restrict__ W2,  const float* __restrict__ b2,
            const float* __restrict__ g2,  const float* __restrict__ be2,
            float* __restrict__ out, int n_edges) {
    float* sEdge = smem;                 // 128 x 128 (edge tile, kept for residual)
    float* sW    = smem + 128 * HID;     // 128 x 128 (W1c, then W2)
    float* sBuf  = smem + 2 * 128 * HID; // 128 x 128 (gather -> pre1 -> h1 -> pre2)

    const int tid  = threadIdx.x;
    const int wid  = tid >> 5;   // 0..15
    const int lane = tid & 31;
    const int e0   = blockIdx.x * 128;

    // W1c = W1 rows 256..383
    for (int i = tid; i < 128 * 32; i += 512)
        ((float4*)sW)[i] = ((const float4*)(W1 + 256 * HID))[i];

    // Edge tile + gathered node transforms (+b1) into sBuf.
    {
        float4 bv = ((const float4*)b1)[lane];
        for (int r = wid; r < 128; r += 16) {
            int e = e0 + r;
            if (e < n_edges) {
                float4 ev = ((const float4*)(edge + (size_t)e * HID))[lane];
                ((float4*)(sEdge + r * HID))[lane] = ev;
                int s = ei[e];
                int d = ei[n_edges + e];
                float4 va = ((const float4*)(g_XA + (size_t)s * HID))[lane];
                float4 vb = ((const float4*)(g_XB + (size_t)d * HID))[lane];
                ((float4*)(sBuf + r * HID))[lane] =
                    make_float4(va.x + vb.x + bv.x, va.y + vb.y + bv.y,
                                va.z + vb.z + bv.z, va.w + vb.w + bv.w);
            } else {
                ((float4*)(sEdge + r * HID))[lane] = make_float4(0.f, 0.f, 0.f, 0.f);
                ((float4*)(sBuf  + r * HID))[lane] = make_float4(0.f, 0.f, 0.f, 0.f);
            }
        }
    }
    __syncthreads();

    const int r0 = (tid >> 5) * 8;
    const int c0 = (tid & 31) * 4;

    // ---- GEMM1: acc = edge @ W1c ----
    float acc[8][4];
    gemm_tile512(sEdge, sW, r0, c0, acc);

    // acc += gathered partials (own float4s only)
#pragma unroll
    for (int i = 0; i < 8; i++) {
        float4 gvv = *(const float4*)(sBuf + (r0 + i) * HID + c0);
        acc[i][0] += gvv.x; acc[i][1] += gvv.y;
        acc[i][2] += gvv.z; acc[i][3] += gvv.w;
    }
    __syncthreads();  // all GEMM1 reads of sW/sBuf done
#pragma unroll
    for (int i = 0; i < 8; i++)
        *(float4*)(sBuf + (r0 + i) * HID + c0) =
            make_float4(acc[i][0], acc[i][1], acc[i][2], acc[i][3]);
    __syncthreads();

    // ---- LN1 + SiLU (warp per row), and reload sW with W2 ----
    {
        float4 gv = ((const float4*)g1)[lane];
        float4 bev = ((const float4*)be1)[lane];
        for (int r = wid; r < 128; r += 16) {
            float4 v = ((float4*)(sBuf + r * HID))[lane];
            float s  = v.x + v.y + v.z + v.w;
            float ss = fmaf(v.x, v.x, fmaf(v.y, v.y, fmaf(v.z, v.z, v.w * v.w)));
#pragma unroll
            for (int o = 16; o > 0; o >>= 1) {
                s  += __shfl_xor_sync(0xffffffffu, s, o);
                ss += __shfl_xor_sync(0xffffffffu, ss, o);
            }
            float mean = s * (1.f / HID);
            float var  = ss * (1.f / HID) - mean * mean;
            float rstd = rsqrtf(var + 1e-5f);
            float y0 = (v.x - mean) * rstd * gv.x + bev.x;
            float y1 = (v.y - mean) * rstd * gv.y + bev.y;
            float y2 = (v.z - mean) * rstd * gv.z + bev.z;
            float y3 = (v.w - mean) * rstd * gv.w + bev.w;
            v.x = y0 / (1.f + __expf(-y0));
            v.y = y1 / (1.f + __expf(-y1));
            v.z = y2 / (1.f + __expf(-y2));
            v.w = y3 / (1.f + __expf(-y3));
            ((float4*)(sBuf + r * HID))[lane] = v;
        }
    }
    for (int i = tid; i < 128 * 32; i += 512)
        ((float4*)sW)[i] = ((const float4*)W2)[i];
    __syncthreads();

    // ---- GEMM2: acc = h1 @ W2 + b2 ----
    gemm_tile512(sBuf, sW, r0, c0, acc);
    {
        float4 b2v = *(const float4*)(b2 + c0);
#pragma unroll
        for (int i = 0; i < 8; i++) {
            acc[i][0] += b2v.x; acc[i][1] += b2v.y;
            acc[i][2] += b2v.z; acc[i][3] += b2v.w;
        }
    }
    __syncthreads();  // all GEMM2 reads of sBuf done
#pragma unroll
    for (int i = 0; i < 8; i++)
        *(float4*)(sBuf + (r0 + i) * HID + c0) =
            make_float4(acc[i][0], acc[i][1], acc[i][2], acc[i][3]);
    __syncthreads();

    // ---- LN2 + tanh + residual -> global ----
    {
        float4 gv = ((const float4*)g2)[lane];
        float4 bev = ((const float4*)be2)[lane];
        for (int r = wid; r < 128; r += 16) {
            float4 v = ((float4*)(sBuf + r * HID))[lane];
            float s  = v.x + v.y + v.z + v.w;
            float ss = fmaf(v.x, v.x, fmaf(v.y, v.y, fmaf(v.z, v.z, v.w * v.w)));
#pragma unroll
            for (int o = 16; o > 0; o >>= 1) {
                s  += __shfl_xor_sync(0xffffffffu, s, o);
                ss += __shfl_xor_sync(0xffffffffu, ss, o);
            }
            float mean = s * (1.f / HID);
            float var  = ss * (1.f / HID) - mean * mean;
            float rstd = rsqrtf(var + 1e-5f);
            int e = e0 + r;
            if (e < n_edges) {
                float4 ev = ((float4*)(sEdge + r * HID))[lane];
                float4 o4;
                o4.x = ev.x + tanhf((v.x - mean) * rstd * gv.x + bev.x);
                o4.y = ev.y + tanhf((v.y - mean) * rstd * gv.y + bev.y);
                o4.z = ev.z + tanhf((v.z - mean) * rstd * gv.z + bev.z);
                o4.w = ev.w + tanhf((v.w - mean) * rstd * gv.w + bev.w);
                ((float4*)(out + (size_t)e * HID))[lane] = o4;
            }
        }
    }
}

extern "C" void kernel_launch(void* const* d_in, const int* in_sizes, int n_in,
                              void* d_out, int out_size) {
    const float* x   = (const float*)d_in[0];
    const int*   ei  = (const int*)d_in[1];      // edge_index: int32
    const float* edg = (const float*)d_in[2];
    const float* W1  = (const float*)d_in[3];
    const float* b1  = (const float*)d_in[4];
    const float* g1  = (const float*)d_in[5];
    const float* be1 = (const float*)d_in[6];
    const float* W2  = (const float*)d_in[7];
    const float* b2  = (const float*)d_in[8];
    const float* g2  = (const float*)d_in[9];
    const float* be2 = (const float*)d_in[10];
    float* out = (float*)d_out;

    int n_nodes = in_sizes[0] / HID;
    int n_edges = in_sizes[2] / HID;
    if (n_nodes > MAXN) n_nodes = MAXN;

    const int SMEM = 3 * 128 * HID * (int)sizeof(float);  // 196608
    cudaFuncSetAttribute(node_kernel, cudaFuncAttributeMaxDynamicSharedMemorySize, SMEM);
    cudaFuncSetAttribute(edge_kernel, cudaFuncAttributeMaxDynamicSharedMemorySize, SMEM);

    int node_blocks = (n_nodes + 127) / 128;
    int edge_blocks = (n_edges + 127) / 128;

    node_kernel<<<node_blocks, 512, SMEM>>>(x, W1, n_nodes);
    edge_kernel<<<edge_blocks, 512, SMEM>>>(edg, ei, W1, b1, g1, be1,
                                            W2, b2, g2, be2, out, n_edges);
}